// round 17
// baseline (speedup 1.0000x reference)
#include <cuda_runtime.h>
#include <cuda_bf16.h>

// Problem: MultinomialCELoss
//   x: [N=8, Q=441, H=128, W=128] f32, y: [N=8, 2, H=128, W=128] f32
//   out[w] = -sum_{n,h} log( x[n, idx(n,h,w), h, w] )
//
// R17: the ~2.1us two-node penalty (8.70 vs 6.62, reproduced 5x) is
// hypothesized to be node-B launch serialization. PDL overlaps it:
// B launches with programmaticStreamSerializationAllowed=1 and blocks in
// cudaGridDependencySynchronize(); A's CTAs call
// cudaTriggerProgrammaticLaunchCompletion() right after their partial stores.
// This unlocks the better dataflow that lost only on node overhead:
//   A: row layout (fully coalesced y, 32x fewer y wavefronts), MLP=2,
//      512 CTAs, transposed partial store (fire-and-forget scatter).
//   B: 128 CTAs, one per w, coalesced L2-hot 2KB read + shuffle tree.

#define N_  8
#define Q_  441
#define H_  128
#define W_  128
#define HW_ (H_ * W_)
#define NBINS 21
#define GRIDA 512             // row-pair groups
#define RPT 2                 // rows per thread (MLP=2: proven optimum)

__device__ float g_partial[W_ * GRIDA];   // 256 KB transposed [w][b]; fully
                                          // overwritten each replay

__device__ __forceinline__ int ab_bin(float v) {
    // Match JAX f32 semantics: floor((v + 110) / 10), clipped to [0,20].
    // __fdiv_rn keeps IEEE division even under fast-math (bin boundaries).
    float q = floorf(__fdiv_rn(v + 110.0f, 10.0f));
    int qi = (int)q;
    qi = qi < 0 ? 0 : qi;
    qi = qi > (NBINS - 1) ? (NBINS - 1) : qi;
    return qi;
}

// Kernel A: CTA b handles flattened rows {2b, 2b+1}. Thread w:
// 4 coalesced y loads -> 2 batched scattered gathers -> 2 MUFU logs ->
// 1 transposed store -> PDL trigger.
__global__ __launch_bounds__(W_) void mce_gather_kernel(
    const float* __restrict__ x,
    const float* __restrict__ y,
    float* __restrict__ partial)
{
    const int w = threadIdx.x;        // 0..127
    const int b = blockIdx.x;         // 0..511

    int idx[RPT], n_[RPT], hw_[RPT];
    #pragma unroll
    for (int k = 0; k < RPT; k++) {
        const int row = b * RPT + k;  // 0..1023
        const int n = row >> 7;
        const int h = row & (H_ - 1);
        n_[k] = n;
        hw_[k] = h * W_ + w;
        float ya = y[(size_t)(n * 2 + 0) * HW_ + hw_[k]];   // coalesced
        float yb = y[(size_t)(n * 2 + 1) * HW_ + hw_[k]];   // coalesced
        idx[k] = ab_bin(ya) * NBINS + ab_bin(yb);
    }

    float v[RPT];
    #pragma unroll
    for (int k = 0; k < RPT; k++) {
        v[k] = x[((size_t)n_[k] * Q_ + idx[k]) * HW_ + hw_[k]];
    }

    float acc = 0.0f;
    #pragma unroll
    for (int k = 0; k < RPT; k++) acc += __logf(v[k]);

    // Transposed, fire-and-forget store: makes kernel B's read coalesced.
    partial[w * GRIDA + b] = acc;

    // PDL: signal this CTA's writes are done so B's gridsync can release
    // as soon as ALL of A's CTAs have triggered (memory visibility included).
    cudaTriggerProgrammaticLaunchCompletion();
}

// Kernel B: launched with PDL overlap; blocks until A completes+flushes,
// then CTA w reads its 512 contiguous L2-hot partials and tree-reduces.
__global__ __launch_bounds__(GRIDA) void mce_reduce_kernel(
    const float* __restrict__ partial,
    float* __restrict__ out)
{
    const int w = blockIdx.x;         // 0..127
    const int t = threadIdx.x;        // 0..511

    cudaGridDependencySynchronize();

    float s = partial[w * GRIDA + t];

    #pragma unroll
    for (int off = 16; off > 0; off >>= 1)
        s += __shfl_down_sync(0xffffffffu, s, off);

    __shared__ float red[GRIDA / 32];     // 16 warp partials
    if ((t & 31) == 0) red[t >> 5] = s;
    __syncthreads();

    if (t < 32) {
        float r = (t < GRIDA / 32) ? red[t] : 0.0f;
        #pragma unroll
        for (int off = 8; off > 0; off >>= 1)
            r += __shfl_down_sync(0xffffffffu, r, off);
        if (t == 0) out[w] = -r;
    }
}

extern "C" void kernel_launch(void* const* d_in, const int* in_sizes, int n_in,
                              void* d_out, int out_size) {
    const float* x = (const float*)d_in[0];
    const float* y = (const float*)d_in[1];
    float* out = (float*)d_out;

    float* partial = nullptr;
    cudaGetSymbolAddress((void**)&partial, g_partial);

    mce_gather_kernel<<<GRIDA, W_>>>(x, y, partial);

    // Launch B with programmatic stream serialization: it may begin before A
    // drains; its gridsync provides the ordering.
    cudaLaunchConfig_t cfg = {};
    cfg.gridDim = dim3(W_);
    cfg.blockDim = dim3(GRIDA);
    cfg.dynamicSmemBytes = 0;
    cudaLaunchAttribute attr[1];
    attr[0].id = cudaLaunchAttributeProgrammaticStreamSerialization;
    attr[0].val.programmaticStreamSerializationAllowed = 1;
    cfg.attrs = attr;
    cfg.numAttrs = 1;
    cudaLaunchKernelEx(&cfg, mce_reduce_kernel,
                       (const float*)partial, out);
}